// round 3
// baseline (speedup 1.0000x reference)
#include <cuda_runtime.h>

#define TM        4
#define NTHREADS  256
#define M_DIM     8192
#define N_DIM     8192

typedef unsigned long long u64;

// ---- packed f32x2 helpers (sm_103a) ----
__device__ __forceinline__ u64 pack2(float a, float b) {
    u64 r;
    asm("mov.b64 %0, {%1, %2};" : "=l"(r) : "f"(a), "f"(b));
    return r;
}
__device__ __forceinline__ u64 fma2(u64 a, u64 b, u64 c) {
    u64 d;
    asm("fma.rn.f32x2 %0, %1, %2, %3;" : "=l"(d) : "l"(a), "l"(b), "l"(c));
    return d;
}
__device__ __forceinline__ void unpack2(u64 v, float& a, float& b) {
    asm("mov.b64 {%0, %1}, %2;" : "=f"(a), "=f"(b) : "l"(v));
}

// y[r][m] = sum_n code[nib(m,n)] * absmax[(m*N+n)/64] * x[r][n] + bias[m]
// qweight: one packed byte per int32. High nibble = even n, low nibble = odd n.
//
// Block: TM=4 rows of W, all of N. 8 warps split N (512 int32 / row each).
// Codebook stored in smem as broadcast u64 pairs (c,c): one conflict-free
// LDS.64 produces the fma2 operand directly; address = single LOP3.
__global__ void __launch_bounds__(NTHREADS, 3)
fp4_gemv_kernel(const float* __restrict__ x,
                const int*   __restrict__ qweight,
                const float* __restrict__ absmax,
                const float* __restrict__ code,
                const float* __restrict__ bias,
                float*       __restrict__ out)
{
    __shared__ u64   code2_sh[16];         // (c,c) pairs: banks 2i,2i+1 -> conflict-free
    __shared__ float red[8][TM * 4];

    const int tid = threadIdx.x;
    const int w   = tid >> 5;
    const int l   = tid & 31;

    if (tid < 16) {
        float v = code[tid];
        code2_sh[tid] = pack2(v, v);
    }
    __syncthreads();

    const int m0 = blockIdx.x * TM;
    const int4* __restrict__ qw4 = (const int4*)qweight;
    const char* cb = (const char*)code2_sh;

    u64 acc01[TM], acc23[TM];   // rows (r0,r1) and (r2,r3) packed
    #pragma unroll
    for (int i = 0; i < TM; ++i) { acc01[i] = 0ULL; acc23[i] = 0ULL; }

    #pragma unroll
    for (int c = 0; c < 4; ++c) {
        const int col4  = w * 128 + c * 32 + l;   // int4 index within row [0,1024)
        const int n0    = col4 * 8;               // first weight column
        const int amcol = col4 >> 3;              // absmax block within row

        // batch ALL global loads up front for max MLP
        int4  q[TM];
        float am[TM];
        #pragma unroll
        for (int mi = 0; mi < TM; ++mi) {
            const int m = m0 + mi;
            q[mi]  = __ldg(&qw4[m * 1024 + col4]);
            am[mi] = __ldg(&absmax[m * 128 + amcol]);
        }

        float4 r0a = __ldg((const float4*)(x + 0 * N_DIM + n0));
        float4 r0b = __ldg((const float4*)(x + 0 * N_DIM + n0 + 4));
        float4 r1a = __ldg((const float4*)(x + 1 * N_DIM + n0));
        float4 r1b = __ldg((const float4*)(x + 1 * N_DIM + n0 + 4));
        float4 r2a = __ldg((const float4*)(x + 2 * N_DIM + n0));
        float4 r2b = __ldg((const float4*)(x + 2 * N_DIM + n0 + 4));
        float4 r3a = __ldg((const float4*)(x + 3 * N_DIM + n0));
        float4 r3b = __ldg((const float4*)(x + 3 * N_DIM + n0 + 4));

        u64 xp01[8], xp23[8];
        xp01[0] = pack2(r0a.x, r1a.x); xp01[1] = pack2(r0a.y, r1a.y);
        xp01[2] = pack2(r0a.z, r1a.z); xp01[3] = pack2(r0a.w, r1a.w);
        xp01[4] = pack2(r0b.x, r1b.x); xp01[5] = pack2(r0b.y, r1b.y);
        xp01[6] = pack2(r0b.z, r1b.z); xp01[7] = pack2(r0b.w, r1b.w);
        xp23[0] = pack2(r2a.x, r3a.x); xp23[1] = pack2(r2a.y, r3a.y);
        xp23[2] = pack2(r2a.z, r3a.z); xp23[3] = pack2(r2a.w, r3a.w);
        xp23[4] = pack2(r2b.x, r3b.x); xp23[5] = pack2(r2b.y, r3b.y);
        xp23[6] = pack2(r2b.z, r3b.z); xp23[7] = pack2(r2b.w, r3b.w);

        #pragma unroll
        for (int mi = 0; mi < TM; ++mi) {
            u64 t01 = 0ULL, t23 = 0ULL;
            const unsigned bb[4] = { (unsigned)q[mi].x, (unsigned)q[mi].y,
                                     (unsigned)q[mi].z, (unsigned)q[mi].w };
            #pragma unroll
            for (int j = 0; j < 4; ++j) {
                const unsigned b = bb[j];                       // 0..255
                // hi nibble -> even column, lo nibble -> odd column
                const u64 ch2 = *(const u64*)(cb + ((b >> 1) & 0x78u));
                const u64 cl2 = *(const u64*)(cb + ((b << 3) & 0x78u));
                t01 = fma2(ch2, xp01[2 * j],     t01);
                t01 = fma2(cl2, xp01[2 * j + 1], t01);
                t23 = fma2(ch2, xp23[2 * j],     t23);
                t23 = fma2(cl2, xp23[2 * j + 1], t23);
            }
            const u64 am2 = pack2(am[mi], am[mi]);
            acc01[mi] = fma2(t01, am2, acc01[mi]);
            acc23[mi] = fma2(t23, am2, acc23[mi]);
        }
    }

    // ---- reduction: warp shfl, then cross-warp via smem ----
    float vals[TM * 4];
    #pragma unroll
    for (int mi = 0; mi < TM; ++mi) {
        unpack2(acc01[mi], vals[mi * 4 + 0], vals[mi * 4 + 1]);
        unpack2(acc23[mi], vals[mi * 4 + 2], vals[mi * 4 + 3]);
    }
    #pragma unroll
    for (int i = 0; i < TM * 4; ++i) {
        float v = vals[i];
        v += __shfl_xor_sync(0xffffffffu, v, 16);
        v += __shfl_xor_sync(0xffffffffu, v, 8);
        v += __shfl_xor_sync(0xffffffffu, v, 4);
        v += __shfl_xor_sync(0xffffffffu, v, 2);
        v += __shfl_xor_sync(0xffffffffu, v, 1);
        vals[i] = v;
    }
    if (l == 0) {
        #pragma unroll
        for (int i = 0; i < TM * 4; ++i) red[w][i] = vals[i];
    }
    __syncthreads();

    if (tid < TM * 4) {
        float s = 0.0f;
        #pragma unroll
        for (int ww = 0; ww < 8; ++ww) s += red[ww][tid];
        const int mi = tid >> 2;
        const int r  = tid & 3;
        out[r * M_DIM + m0 + mi] = s + bias[m0 + mi];
    }
}

extern "C" void kernel_launch(void* const* d_in, const int* in_sizes, int n_in,
                              void* d_out, int out_size)
{
    const float* x       = (const float*)d_in[0];
    const int*   qweight = (const int*)  d_in[1];
    const float* absmax  = (const float*)d_in[2];
    const float* code    = (const float*)d_in[3];
    const float* bias    = (const float*)d_in[4];
    float*       out     = (float*)d_out;

    fp4_gemv_kernel<<<M_DIM / TM, NTHREADS>>>(x, qweight, absmax, code, bias, out);
}

// round 4
// speedup vs baseline: 1.3009x; 1.3009x over previous
#include <cuda_runtime.h>

#define TM        8
#define NTHREADS  128
#define M_DIM     8192
#define N_DIM     8192

typedef unsigned long long u64;

// ---- packed f32x2 helpers (sm_103a) ----
__device__ __forceinline__ u64 pack2(float a, float b) {
    u64 r;
    asm("mov.b64 %0, {%1, %2};" : "=l"(r) : "f"(a), "f"(b));
    return r;
}
__device__ __forceinline__ u64 fma2(u64 a, u64 b, u64 c) {
    u64 d;
    asm("fma.rn.f32x2 %0, %1, %2, %3;" : "=l"(d) : "l"(a), "l"(b), "l"(c));
    return d;
}
__device__ __forceinline__ void unpack2(u64 v, float& a, float& b) {
    asm("mov.b64 {%0, %1}, %2;" : "=f"(a), "=f"(b) : "l"(v));
}

// y[r][m] = sum_n code[nib(m,n)] * absmax[(m*N+n)/64] * x[r][n] + bias[m]
// qweight: one packed byte per int32. High nibble = even n, low nibble = odd n.
//
// Block: TM=8 rows of W, all of N. 4 warps; warp covers cols in 8 chunks of
// 32 int4. Software pipeline: double-buffer q/absmax per 4-row group so DRAM
// latency overlaps the previous group's decode.
__global__ void __launch_bounds__(NTHREADS, 4)
fp4_gemv_kernel(const float* __restrict__ x,
                const int*   __restrict__ qweight,
                const float* __restrict__ absmax,
                const float* __restrict__ code,
                const float* __restrict__ bias,
                float*       __restrict__ out)
{
    __shared__ float code_sh[16];          // 16 floats = 16 banks: conflict-free
    __shared__ float red[4][32];

    const int tid = threadIdx.x;
    const int w   = tid >> 5;
    const int l   = tid & 31;

    if (tid < 16) code_sh[tid] = code[tid];
    __syncthreads();

    const int m0 = blockIdx.x * TM;
    const int4* __restrict__ qw4 = (const int4*)qweight;

    u64 acc01[TM], acc23[TM];   // rows (r0,r1) and (r2,r3) packed
    #pragma unroll
    for (int i = 0; i < TM; ++i) { acc01[i] = 0ULL; acc23[i] = 0ULL; }

    const int lane_col = w * 32 + l;       // col4 base within each chunk of 128

    int4  qb[2][4];
    float amb[2][4];

    // prologue: step 0 = (chunk 0, group 0) into buffer 0
    #pragma unroll
    for (int mi = 0; mi < 4; ++mi) {
        qb[0][mi]  = __ldg(&qw4[(m0 + mi) * 1024 + lane_col]);
        amb[0][mi] = __ldg(&absmax[(m0 + mi) * 128 + (lane_col >> 3)]);
    }

    #pragma unroll 2
    for (int c = 0; c < 8; ++c) {
        const int col4 = c * 128 + lane_col;
        const int n0   = col4 * 8;

        // x is L1/L2-hot (128KB total); loads reused across all 8 rows
        float4 r0a = __ldg((const float4*)(x + 0 * N_DIM + n0));
        float4 r0b = __ldg((const float4*)(x + 0 * N_DIM + n0 + 4));
        float4 r1a = __ldg((const float4*)(x + 1 * N_DIM + n0));
        float4 r1b = __ldg((const float4*)(x + 1 * N_DIM + n0 + 4));
        float4 r2a = __ldg((const float4*)(x + 2 * N_DIM + n0));
        float4 r2b = __ldg((const float4*)(x + 2 * N_DIM + n0 + 4));
        float4 r3a = __ldg((const float4*)(x + 3 * N_DIM + n0));
        float4 r3b = __ldg((const float4*)(x + 3 * N_DIM + n0 + 4));

        u64 xp01[8], xp23[8];
        xp01[0] = pack2(r0a.x, r1a.x); xp01[1] = pack2(r0a.y, r1a.y);
        xp01[2] = pack2(r0a.z, r1a.z); xp01[3] = pack2(r0a.w, r1a.w);
        xp01[4] = pack2(r0b.x, r1b.x); xp01[5] = pack2(r0b.y, r1b.y);
        xp01[6] = pack2(r0b.z, r1b.z); xp01[7] = pack2(r0b.w, r1b.w);
        xp23[0] = pack2(r2a.x, r3a.x); xp23[1] = pack2(r2a.y, r3a.y);
        xp23[2] = pack2(r2a.z, r3a.z); xp23[3] = pack2(r2a.w, r3a.w);
        xp23[4] = pack2(r2b.x, r3b.x); xp23[5] = pack2(r2b.y, r3b.y);
        xp23[6] = pack2(r2b.z, r3b.z); xp23[7] = pack2(r2b.w, r3b.w);

        #pragma unroll
        for (int g = 0; g < 2; ++g) {
            const int s = c * 2 + g;       // pipeline step, 0..15
            const int p = g;               // buffer parity (== s&1)

            // prefetch next step's q + absmax into the other buffer
            if (s < 15) {
                const int sn    = s + 1;
                const int cn    = sn >> 1;
                const int gn    = sn & 1;
                const int col4n = cn * 128 + lane_col;
                #pragma unroll
                for (int mi = 0; mi < 4; ++mi) {
                    const int m = m0 + gn * 4 + mi;
                    qb[p ^ 1][mi]  = __ldg(&qw4[m * 1024 + col4n]);
                    amb[p ^ 1][mi] = __ldg(&absmax[m * 128 + (col4n >> 3)]);
                }
            }

            // decode + accumulate current group (buffer p)
            #pragma unroll
            for (int mi = 0; mi < 4; ++mi) {
                u64 t01 = 0ULL, t23 = 0ULL;
                const unsigned bb[4] = { (unsigned)qb[p][mi].x, (unsigned)qb[p][mi].y,
                                         (unsigned)qb[p][mi].z, (unsigned)qb[p][mi].w };
                #pragma unroll
                for (int j = 0; j < 4; ++j) {
                    const unsigned b = bb[j];            // 0..255
                    const float chi = code_sh[b >> 4];   // even column
                    const float clo = code_sh[b & 15];   // odd column
                    const u64 ch2 = pack2(chi, chi);
                    const u64 cl2 = pack2(clo, clo);
                    t01 = fma2(ch2, xp01[2 * j],     t01);
                    t01 = fma2(cl2, xp01[2 * j + 1], t01);
                    t23 = fma2(ch2, xp23[2 * j],     t23);
                    t23 = fma2(cl2, xp23[2 * j + 1], t23);
                }
                const u64 am2 = pack2(amb[p][mi], amb[p][mi]);
                const int ai = g * 4 + mi;
                acc01[ai] = fma2(t01, am2, acc01[ai]);
                acc23[ai] = fma2(t23, am2, acc23[ai]);
            }
        }
    }

    // ---- reduction: warp shfl, then cross-warp via smem ----
    float vals[TM * 4];
    #pragma unroll
    for (int mi = 0; mi < TM; ++mi) {
        unpack2(acc01[mi], vals[mi * 4 + 0], vals[mi * 4 + 1]);
        unpack2(acc23[mi], vals[mi * 4 + 2], vals[mi * 4 + 3]);
    }
    #pragma unroll
    for (int i = 0; i < TM * 4; ++i) {
        float v = vals[i];
        v += __shfl_xor_sync(0xffffffffu, v, 16);
        v += __shfl_xor_sync(0xffffffffu, v, 8);
        v += __shfl_xor_sync(0xffffffffu, v, 4);
        v += __shfl_xor_sync(0xffffffffu, v, 2);
        v += __shfl_xor_sync(0xffffffffu, v, 1);
        vals[i] = v;
    }
    if (l == 0) {
        #pragma unroll
        for (int i = 0; i < TM * 4; ++i) red[w][i] = vals[i];
    }
    __syncthreads();

    if (tid < TM * 4) {
        float s = red[0][tid] + red[1][tid] + red[2][tid] + red[3][tid];
        const int mi = tid >> 2;
        const int r  = tid & 3;
        out[r * M_DIM + m0 + mi] = s + bias[m0 + mi];
    }
}

extern "C" void kernel_launch(void* const* d_in, const int* in_sizes, int n_in,
                              void* d_out, int out_size)
{
    const float* x       = (const float*)d_in[0];
    const int*   qweight = (const int*)  d_in[1];
    const float* absmax  = (const float*)d_in[2];
    const float* code    = (const float*)d_in[3];
    const float* bias    = (const float*)d_in[4];
    float*       out     = (float*)d_out;

    fp4_gemv_kernel<<<M_DIM / TM, NTHREADS>>>(x, qweight, absmax, code, bias, out);
}

// round 6
// speedup vs baseline: 1.3428x; 1.0322x over previous
#include <cuda_runtime.h>

#define TM        4
#define NTHREADS  128
#define M_DIM     8192
#define N_DIM     8192

typedef unsigned long long u64;

// ---- packed f32x2 helpers (sm_103a) ----
__device__ __forceinline__ u64 pack2(float a, float b) {
    u64 r;
    asm("mov.b64 %0, {%1, %2};" : "=l"(r) : "f"(a), "f"(b));
    return r;
}
__device__ __forceinline__ u64 fma2(u64 a, u64 b, u64 c) {
    u64 d;
    asm("fma.rn.f32x2 %0, %1, %2, %3;" : "=l"(d) : "l"(a), "l"(b), "l"(c));
    return d;
}
__device__ __forceinline__ void unpack2(u64 v, float& a, float& b) {
    asm("mov.b64 {%0, %1}, %2;" : "=f"(a), "=f"(b) : "l"(v));
}

// y[r][m] = sum_n code[nib(m,n)] * absmax[(m*N+n)/64] * x[r][n] + bias[m]
// qweight int32 value is one packed byte (0..255): hi nibble = even col,
// lo nibble = odd col.
//
// Natural (even,odd) f32x2 packing:
//   x float4 halves ARE (even,odd) pairs -> ulonglong2 loads, zero pack movs.
//   weight pair (chi,clo) packed once per byte, reused across 4 x-rows.
//   acc[m][r] = (sum_even, sum_odd); halves summed once in epilogue.
__global__ void __launch_bounds__(NTHREADS, 4)
fp4_gemv_kernel(const float* __restrict__ x,
                const int*   __restrict__ qweight,
                const float* __restrict__ absmax,
                const float* __restrict__ code,
                const float* __restrict__ bias,
                float*       __restrict__ out)
{
    __shared__ float code_sh[16];          // 16 floats = 16 banks: conflict-free
    __shared__ float red[4][TM * 4];

    const int tid = threadIdx.x;
    const int w   = tid >> 5;
    const int l   = tid & 31;

    if (tid < 16) code_sh[tid] = code[tid];
    __syncthreads();

    const int m0 = blockIdx.x * TM;
    const int4* __restrict__ qw4 = (const int4*)qweight;

    u64 acc[TM][4];                        // [w-row][x-row] = (even,odd) sums
    #pragma unroll
    for (int mi = 0; mi < TM; ++mi)
        #pragma unroll
        for (int r = 0; r < 4; ++r) acc[mi][r] = 0ULL;

    const int lane_col = w * 32 + l;       // col4 base within each chunk of 128

    #pragma unroll 2
    for (int c = 0; c < 8; ++c) {
        const int col4 = c * 128 + lane_col;   // int4 index in row [0,1024)
        const int n0   = col4 * 8;             // first weight column

        // ---- batch all global loads up front (max MLP) ----
        int4  q[TM];
        float am[TM];
        #pragma unroll
        for (int mi = 0; mi < TM; ++mi) {
            q[mi]  = __ldg(&qw4[(m0 + mi) * 1024 + col4]);
            am[mi] = __ldg(&absmax[(m0 + mi) * 128 + (col4 >> 3)]);
        }

        // x pairs: xp[j][r] = (x[r][n0+2j], x[r][n0+2j+1]) — no packing needed
        u64 xp[4][4];
        #pragma unroll
        for (int r = 0; r < 4; ++r) {
            ulonglong2 a = __ldg((const ulonglong2*)(x + r * N_DIM + n0));
            ulonglong2 b = __ldg((const ulonglong2*)(x + r * N_DIM + n0 + 4));
            xp[0][r] = a.x; xp[1][r] = a.y;
            xp[2][r] = b.x; xp[3][r] = b.y;
        }

        // ---- decode + accumulate ----
        #pragma unroll
        for (int mi = 0; mi < TM; ++mi) {
            const unsigned bb[4] = { (unsigned)q[mi].x, (unsigned)q[mi].y,
                                     (unsigned)q[mi].z, (unsigned)q[mi].w };
            u64 t[4] = {0ULL, 0ULL, 0ULL, 0ULL};   // per x-row, unscaled
            #pragma unroll
            for (int j = 0; j < 4; ++j) {
                const unsigned b = bb[j];                    // 0..255
                const u64 c2 = pack2(code_sh[b >> 4], code_sh[b & 15]);
                t[0] = fma2(c2, xp[j][0], t[0]);
                t[1] = fma2(c2, xp[j][1], t[1]);
                t[2] = fma2(c2, xp[j][2], t[2]);
                t[3] = fma2(c2, xp[j][3], t[3]);
            }
            const u64 am2 = pack2(am[mi], am[mi]);
            #pragma unroll
            for (int r = 0; r < 4; ++r)
                acc[mi][r] = fma2(t[r], am2, acc[mi][r]);
        }
    }

    // ---- epilogue: halves sum (free unpack), shfl reduce, cross-warp ----
    float vals[TM * 4];
    #pragma unroll
    for (int mi = 0; mi < TM; ++mi)
        #pragma unroll
        for (int r = 0; r < 4; ++r) {
            float e, o;
            unpack2(acc[mi][r], e, o);
            vals[mi * 4 + r] = e + o;
        }
    #pragma unroll
    for (int i = 0; i < TM * 4; ++i) {
        float v = vals[i];
        v += __shfl_xor_sync(0xffffffffu, v, 16);
        v += __shfl_xor_sync(0xffffffffu, v, 8);
        v += __shfl_xor_sync(0xffffffffu, v, 4);
        v += __shfl_xor_sync(0xffffffffu, v, 2);
        v += __shfl_xor_sync(0xffffffffu, v, 1);
        vals[i] = v;
    }
    if (l == 0) {
        #pragma unroll
        for (int i = 0; i < TM * 4; ++i) red[w][i] = vals[i];
    }
    __syncthreads();

    if (tid < TM * 4) {
        float s = red[0][tid] + red[1][tid] + red[2][tid] + red[3][tid];
        const int mi = tid >> 2;
        const int r  = tid & 3;
        out[r * M_DIM + m0 + mi] = s + bias[m0 + mi];
    }
}

extern "C" void kernel_launch(void* const* d_in, const int* in_sizes, int n_in,
                              void* d_out, int out_size)
{
    const float* x       = (const float*)d_in[0];
    const int*   qweight = (const int*)  d_in[1];
    const float* absmax  = (const float*)d_in[2];
    const float* code    = (const float*)d_in[3];
    const float* bias    = (const float*)d_in[4];
    float*       out     = (float*)d_out;

    fp4_gemv_kernel<<<M_DIM / TM, NTHREADS>>>(x, qweight, absmax, code, bias, out);
}